// round 4
// baseline (speedup 1.0000x reference)
#include <cuda_runtime.h>
#include <cuda_bf16.h>
#include <cstdint>

// ---------------------------------------------------------------------------
// Problem constants
// ---------------------------------------------------------------------------
constexpr int B_ = 4;
constexpr int N_ = 2048;
constexpr int D_ = 1024;
constexpr int M_ = B_ * N_;  // 8192 tokens

// ---------------------------------------------------------------------------
// Scratch (device globals — allocation is forbidden)
// ---------------------------------------------------------------------------
__device__ __nv_bfloat16 g_xh[M_ * D_], g_xl[M_ * D_];
__device__ __nv_bfloat16 g_Wth[3][D_ * D_], g_Wtl[3][D_ * D_];  // W^T [e][d]
__device__ __nv_bfloat16 g_Qh[M_ * D_], g_Ql[M_ * D_];
__device__ __nv_bfloat16 g_Kh[M_ * D_], g_Kl[M_ * D_];
__device__ __nv_bfloat16 g_Vh[M_ * D_], g_Vl[M_ * D_];
__device__ __nv_bfloat16 g_Vth[B_][D_ * N_], g_Vtl[B_][D_ * N_];  // V^T [e][tok]
__device__ float g_S[(size_t)B_ * N_ * N_];
__device__ __nv_bfloat16 g_Ph[(size_t)B_ * N_ * N_], g_Pl[(size_t)B_ * N_ * N_];

// ---------------------------------------------------------------------------
// Helpers
// ---------------------------------------------------------------------------
__device__ __forceinline__ uint32_t smem_u32(const void* p) {
  uint32_t a;
  asm("{ .reg .u64 t; cvta.to.shared.u64 t, %1; cvt.u32.u64 %0, t; }"
      : "=r"(a) : "l"(p));
  return a;
}

__device__ __forceinline__ void cp_async16(uint32_t smem, const void* g) {
  asm volatile("cp.async.cg.shared.global [%0], [%1], 16;" ::"r"(smem), "l"(g)
               : "memory");
}
#define CP_COMMIT() asm volatile("cp.async.commit_group;" ::: "memory")

__device__ __forceinline__ uint32_t swz128(uint32_t off) {
  return off ^ ((off >> 3) & 0x70);
}

__device__ __forceinline__ void ldmatrix_x4(uint32_t& r0, uint32_t& r1,
                                            uint32_t& r2, uint32_t& r3,
                                            uint32_t addr) {
  asm volatile(
      "ldmatrix.sync.aligned.m8n8.x4.shared.b16 {%0,%1,%2,%3}, [%4];"
      : "=r"(r0), "=r"(r1), "=r"(r2), "=r"(r3)
      : "r"(addr));
}

__device__ __forceinline__ void mma_bf16(float* c, const uint32_t* a,
                                         uint32_t b0, uint32_t b1) {
  asm volatile(
      "mma.sync.aligned.m16n8k16.row.col.f32.bf16.bf16.f32 "
      "{%0,%1,%2,%3}, {%4,%5,%6,%7}, {%8,%9}, {%0,%1,%2,%3};"
      : "+f"(c[0]), "+f"(c[1]), "+f"(c[2]), "+f"(c[3])
      : "r"(a[0]), "r"(a[1]), "r"(a[2]), "r"(a[3]), "r"(b0), "r"(b1));
}

// ---------------------------------------------------------------------------
// Warp-tiled bf16 mma.sync GEMM, C[128x256] = A[128,K'] * B[256,K']^T.
// Both operands K-major. K' = hi/lo-tripled contraction:
// segments [A_hi*B_hi, A_lo*B_hi, A_hi*B_lo].
// 512 threads, 16 warps in 4x4; warp tile 32x64. 3-stage cp.async pipeline.
// mode 0: QKV proj (z=matrix)  mode 1: scores (z=batch)  mode 2: PV (z=batch)
// ---------------------------------------------------------------------------
constexpr int ASTG = 16384;   // 128 rows x 128B (BK = 64 bf16)
constexpr int BSTG = 32768;   // 256 rows x 128B
constexpr int STG = ASTG + BSTG;
constexpr int SMEM_DYN = 1024 + 3 * STG;  // 148480
constexpr float SCALE = 0.03125f;  // 1/sqrt(1024)

__global__ __launch_bounds__(512, 1) void gemm_tc(int mode, float* out) {
  extern __shared__ char dsm[];

  const int bx = blockIdx.x, by = blockIdx.y, bz = blockIdx.z;
  const int row0 = by * 128, col0 = bx * 256;

  const __nv_bfloat16 *aH, *aL, *bH, *bL;
  size_t lda, ldb;
  int nk;
  if (mode == 0) {
    aH = g_xh; aL = g_xl;
    bH = g_Wth[bz]; bL = g_Wtl[bz];
    lda = D_; ldb = D_; nk = 16;
  } else if (mode == 1) {
    if (col0 > row0 + 127) return;  // tile fully above the diagonal
    size_t o = (size_t)bz * N_ * D_;
    aH = g_Qh + o; aL = g_Ql + o;
    bH = g_Kh + o; bL = g_Kl + o;
    lda = D_; ldb = D_; nk = 16;
  } else {
    size_t oa = (size_t)bz * N_ * N_;
    aH = g_Ph + oa; aL = g_Pl + oa;
    bH = g_Vth[bz]; bL = g_Vtl[bz];
    lda = N_; ldb = N_; nk = (row0 + 128) / 64;  // causal K bound
  }
  const int nchunks = 3 * nk;

  const int tid = threadIdx.x;
  const int wid = tid >> 5, lid = tid & 31;
  const int wm = wid & 3, wn = wid >> 2;  // 4x4 warp grid; warp tile 32x64

  const uint32_t smA = (smem_u32(dsm) + 1023) & ~1023u;

  float acc[2][8][4];
#pragma unroll
  for (int i = 0; i < 2; ++i)
#pragma unroll
    for (int j = 0; j < 8; ++j)
#pragma unroll
      for (int k = 0; k < 4; ++k) acc[i][j][k] = 0.f;

  // ---- chunk loader: 512 threads; A 2x cp16, B 4x cp16 per thread ----
  auto load_chunk = [&](int c, int s) {
    const int seg = c / nk;
    const int k0 = (c - seg * nk) * 64;
    const __nv_bfloat16* a = (seg == 1) ? aL : aH;
    const __nv_bfloat16* b = (seg == 2) ? bL : bH;
    const uint32_t sa = smA + s * STG;
    const uint32_t sb = sa + ASTG;
    {  // A: 128 rows x 128B; thread t: row t>>2, quarter t&3
      const int r = tid >> 2, h = tid & 3;
      const uint32_t o0 = (uint32_t)(r * 128 + h * 32);
      const char* ag = (const char*)(a + (size_t)(row0 + r) * lda + k0) + h * 32;
#pragma unroll
      for (int j = 0; j < 2; ++j)
        cp_async16(sa + swz128(o0 + j * 16), ag + j * 16);
    }
    {  // B: 256 rows x 128B; thread t: row t>>1, half t&1
      const int r = tid >> 1, h = tid & 1;
      const uint32_t o0 = (uint32_t)(r * 128 + h * 64);
      const char* bg = (const char*)(b + (size_t)(col0 + r) * ldb + k0) + h * 64;
#pragma unroll
      for (int j = 0; j < 4; ++j)
        cp_async16(sb + swz128(o0 + j * 16), bg + j * 16);
    }
    CP_COMMIT();
  };

  load_chunk(0, 0);
  load_chunk(1, 1);

  for (int c = 0; c < nchunks; ++c) {
    if (c + 1 < nchunks)
      asm volatile("cp.async.wait_group 1;" ::: "memory");
    else
      asm volatile("cp.async.wait_group 0;" ::: "memory");
    __syncthreads();
    // stage (c+2)%3 is free: its previous reader (chunk c-1) finished
    // before the barrier above. Issue its loads, then compute chunk c.
    if (c + 2 < nchunks) load_chunk(c + 2, (c + 2) % 3);

    const uint32_t sa = smA + (c % 3) * STG;
    const uint32_t sb = sa + ASTG;

#pragma unroll
    for (int kk = 0; kk < 4; ++kk) {  // 4 x k16 per 64-wide chunk
      uint32_t af[2][4];
#pragma unroll
      for (int mt = 0; mt < 2; ++mt) {
        const int m0 = wm * 32 + mt * 16;
        const int row = m0 + ((lid >> 3) & 1) * 8 + (lid & 7);
        const int kb = kk * 32 + ((lid >> 4) & 1) * 16;
        ldmatrix_x4(af[mt][0], af[mt][1], af[mt][2], af[mt][3],
                    sa + row * 128 + (kb ^ ((row & 7) << 4)));
      }
      uint32_t bfr[4][4];
#pragma unroll
      for (int np = 0; np < 4; ++np) {
        const int n0 = wn * 64 + np * 16;
        const int row = n0 + ((lid >> 4) & 1) * 8 + (lid & 7);
        const int kb = kk * 32 + ((lid >> 3) & 1) * 16;
        ldmatrix_x4(bfr[np][0], bfr[np][1], bfr[np][2], bfr[np][3],
                    sb + row * 128 + (kb ^ ((row & 7) << 4)));
      }
#pragma unroll
      for (int mt = 0; mt < 2; ++mt)
#pragma unroll
        for (int nt = 0; nt < 8; ++nt)
          mma_bf16(acc[mt][nt], af[mt], bfr[nt >> 1][(nt & 1) * 2],
                   bfr[nt >> 1][(nt & 1) * 2 + 1]);
    }
    __syncthreads();
  }

  // ---- epilogue: fragment (c0,c1)=(m, n..n+1), (c2,c3)=(m+8, n..n+1) ----
#pragma unroll
  for (int mt = 0; mt < 2; ++mt) {
#pragma unroll
    for (int nt = 0; nt < 8; ++nt) {
      const int m = row0 + wm * 32 + mt * 16 + (lid >> 2);
      const int n = col0 + wn * 64 + nt * 8 + 2 * (lid & 3);
      const float* cf = acc[mt][nt];
      if (mode == 0) {
        __nv_bfloat16* Ch = (bz == 0) ? g_Qh : (bz == 1) ? g_Kh : g_Vh;
        __nv_bfloat16* Cl = (bz == 0) ? g_Ql : (bz == 1) ? g_Kl : g_Vl;
#pragma unroll
        for (int hh = 0; hh < 2; ++hh) {
          const size_t o = (size_t)(m + hh * 8) * D_ + n;
          float v0 = cf[hh * 2], v1 = cf[hh * 2 + 1];
          __nv_bfloat16 h0 = __float2bfloat16(v0), h1 = __float2bfloat16(v1);
          *(__nv_bfloat162*)(Ch + o) = __nv_bfloat162(h0, h1);
          *(__nv_bfloat162*)(Cl + o) = __nv_bfloat162(
              __float2bfloat16(v0 - __bfloat162float(h0)),
              __float2bfloat16(v1 - __bfloat162float(h1)));
        }
      } else if (mode == 1) {
#pragma unroll
        for (int hh = 0; hh < 2; ++hh) {
          float* sp = g_S + ((size_t)bz * N_ + m + hh * 8) * N_ + n;
          sp[0] = cf[hh * 2] * SCALE;
          sp[1] = cf[hh * 2 + 1] * SCALE;
        }
      } else {
#pragma unroll
        for (int hh = 0; hh < 2; ++hh) {
          float* op = out + ((size_t)bz * N_ + m + hh * 8) * D_ + n;
          op[0] = cf[hh * 2];
          op[1] = cf[hh * 2 + 1];
        }
      }
    }
  }
}

// ---------------------------------------------------------------------------
// Conversions
// ---------------------------------------------------------------------------
__global__ __launch_bounds__(256) void conv_x_kernel(const float* __restrict__ x) {
  size_t i = ((size_t)blockIdx.x * 256 + threadIdx.x) * 4;
  float4 v = *(const float4*)(x + i);
  float vv[4] = {v.x, v.y, v.z, v.w};
#pragma unroll
  for (int j = 0; j < 4; ++j) {
    __nv_bfloat16 h = __float2bfloat16(vv[j]);
    g_xh[i + j] = h;
    g_xl[i + j] = __float2bfloat16(vv[j] - __bfloat162float(h));
  }
}

// transpose-convert W[d][e] -> Wt_hi/lo[e][d]
__global__ __launch_bounds__(256) void conv_w_kernel(const float* __restrict__ Wq,
                                                     const float* __restrict__ Wk,
                                                     const float* __restrict__ Wv) {
  const float* W = (blockIdx.z == 0) ? Wq : (blockIdx.z == 1) ? Wk : Wv;
  __nv_bfloat16* Th = g_Wth[blockIdx.z];
  __nv_bfloat16* Tl = g_Wtl[blockIdx.z];
  __shared__ float t[32][33];
  int tx = threadIdx.x & 31, ty = threadIdx.x >> 5;  // 32 x 8
  int d0 = blockIdx.y * 32, e0 = blockIdx.x * 32;
#pragma unroll
  for (int i = 0; i < 4; ++i)
    t[ty + i * 8][tx] = W[(size_t)(d0 + ty + i * 8) * D_ + e0 + tx];
  __syncthreads();
#pragma unroll
  for (int i = 0; i < 4; ++i) {
    float v = t[tx][ty + i * 8];
    __nv_bfloat16 h = __float2bfloat16(v);
    size_t o = (size_t)(e0 + ty + i * 8) * D_ + d0 + tx;
    Th[o] = h;
    Tl[o] = __float2bfloat16(v - __bfloat162float(h));
  }
}

// transpose V_hi/lo[b][tok][e] -> Vt_hi/lo[b][e][tok]
__global__ __launch_bounds__(256) void conv_vt_kernel() {
  __shared__ uint16_t th[32][33], tl[32][33];
  int tx = threadIdx.x & 31, ty = threadIdx.x >> 5;
  int tok0 = blockIdx.x * 32, e0 = blockIdx.y * 32, b = blockIdx.z;
  const uint16_t* Vh = (const uint16_t*)(g_Vh) + (size_t)b * N_ * D_;
  const uint16_t* Vl = (const uint16_t*)(g_Vl) + (size_t)b * N_ * D_;
#pragma unroll
  for (int i = 0; i < 4; ++i) {
    size_t o = (size_t)(tok0 + ty + i * 8) * D_ + e0 + tx;
    th[ty + i * 8][tx] = Vh[o];
    tl[ty + i * 8][tx] = Vl[o];
  }
  __syncthreads();
  uint16_t* Oh = (uint16_t*)g_Vth[b];
  uint16_t* Ol = (uint16_t*)g_Vtl[b];
#pragma unroll
  for (int i = 0; i < 4; ++i) {
    size_t o = (size_t)(e0 + ty + i * 8) * N_ + tok0 + tx;
    Oh[o] = th[tx][ty + i * 8];
    Ol[o] = tl[tx][ty + i * 8];
  }
}

// ---------------------------------------------------------------------------
// Causal softmax: reads S fp32 (k <= q only), writes P hi/lo bf16, zeros beyond
// ---------------------------------------------------------------------------
__global__ __launch_bounds__(256) void softmax_kernel() {
  const int q = blockIdx.x, b = blockIdx.y;
  const float* row = g_S + ((size_t)b * N_ + q) * N_;
  __nv_bfloat16* ph = g_Ph + ((size_t)b * N_ + q) * N_;
  __nv_bfloat16* pl = g_Pl + ((size_t)b * N_ + q) * N_;
  const int L = q + 1;
  const int tid = threadIdx.x;

  __shared__ float red[256];

  float m = -1e30f;
  for (int k = tid; k < L; k += 256) m = fmaxf(m, row[k]);
  red[tid] = m;
  __syncthreads();
  for (int s = 128; s > 0; s >>= 1) {
    if (tid < s) red[tid] = fmaxf(red[tid], red[tid + s]);
    __syncthreads();
  }
  m = red[0];
  __syncthreads();

  float sum = 0.f;
  for (int k = tid; k < L; k += 256) sum += expf(row[k] - m);
  red[tid] = sum;
  __syncthreads();
  for (int s = 128; s > 0; s >>= 1) {
    if (tid < s) red[tid] += red[tid + s];
    __syncthreads();
  }
  const float inv = 1.f / red[0];

  for (int k = tid; k < N_; k += 256) {
    if (k < L) {
      float p = expf(row[k] - m) * inv;
      __nv_bfloat16 h = __float2bfloat16(p);
      ph[k] = h;
      pl[k] = __float2bfloat16(p - __bfloat162float(h));
    } else {
      ph[k] = __float2bfloat16(0.f);
      pl[k] = __float2bfloat16(0.f);
    }
  }
}

// ---------------------------------------------------------------------------
extern "C" void kernel_launch(void* const* d_in, const int* in_sizes, int n_in,
                              void* d_out, int out_size) {
  const float* x  = (const float*)d_in[0];
  const float* Wq = (const float*)d_in[1];
  const float* Wk = (const float*)d_in[2];
  const float* Wv = (const float*)d_in[3];
  float* out = (float*)d_out;

  cudaFuncSetAttribute(gemm_tc, cudaFuncAttributeMaxDynamicSharedMemorySize,
                       SMEM_DYN);

  // 1) split inputs into bf16 hi/lo
  conv_x_kernel<<<(M_ * D_) / (256 * 4), 256>>>(x);
  conv_w_kernel<<<dim3(D_ / 32, D_ / 32, 3), 256>>>(Wq, Wk, Wv);
  // 2) QKV projections: C[8192,1024], 128x256 tiles
  gemm_tc<<<dim3(D_ / 256, M_ / 128, 3), 512, SMEM_DYN>>>(0, nullptr);
  // 3) transpose V for the PV GEMM
  conv_vt_kernel<<<dim3(N_ / 32, D_ / 32, B_), 256>>>();
  // 4) scores S = scale * Q K^T (tiles above the diagonal skipped)
  gemm_tc<<<dim3(N_ / 256, N_ / 128, B_), 512, SMEM_DYN>>>(1, nullptr);
  // 5) softmax -> P hi/lo
  softmax_kernel<<<dim3(N_, B_), 256>>>();
  // 6) O = P V (causally bounded K loop)
  gemm_tc<<<dim3(D_ / 256, N_ / 128, B_), 512, SMEM_DYN>>>(2, out);
}

// round 5
// speedup vs baseline: 2.7291x; 2.7291x over previous
#include <cuda_runtime.h>
#include <cuda_fp16.h>
#include <cstdint>

// ---------------------------------------------------------------------------
// Problem constants
// ---------------------------------------------------------------------------
constexpr int B_ = 4;
constexpr int N_ = 2048;
constexpr int D_ = 1024;
constexpr int M_ = B_ * N_;  // 8192 tokens

// ---------------------------------------------------------------------------
// Scratch (device globals — allocation is forbidden)
// ---------------------------------------------------------------------------
__device__ __half g_x16[M_ * D_];
__device__ __half g_Wt16[3][D_ * D_];       // W^T [e][d]
__device__ __half g_Q16[M_ * D_];
__device__ __half g_K16[M_ * D_];
__device__ __half g_V16[M_ * D_];
__device__ __half g_Vt16[B_][D_ * N_];      // V^T [e][tok]
__device__ float g_S[(size_t)B_ * N_ * N_];
__device__ __half g_P16[(size_t)B_ * N_ * N_];

// ---------------------------------------------------------------------------
// Helpers
// ---------------------------------------------------------------------------
__device__ __forceinline__ uint32_t smem_u32(const void* p) {
  uint32_t a;
  asm("{ .reg .u64 t; cvta.to.shared.u64 t, %1; cvt.u32.u64 %0, t; }"
      : "=r"(a) : "l"(p));
  return a;
}

__device__ __forceinline__ void cp_async16(uint32_t smem, const void* g) {
  asm volatile("cp.async.cg.shared.global [%0], [%1], 16;" ::"r"(smem), "l"(g)
               : "memory");
}
#define CP_COMMIT() asm volatile("cp.async.commit_group;" ::: "memory")

__device__ __forceinline__ uint32_t swz128(uint32_t off) {
  return off ^ ((off >> 3) & 0x70);
}

__device__ __forceinline__ void ldmatrix_x4(uint32_t& r0, uint32_t& r1,
                                            uint32_t& r2, uint32_t& r3,
                                            uint32_t addr) {
  asm volatile(
      "ldmatrix.sync.aligned.m8n8.x4.shared.b16 {%0,%1,%2,%3}, [%4];"
      : "=r"(r0), "=r"(r1), "=r"(r2), "=r"(r3)
      : "r"(addr));
}

__device__ __forceinline__ void mma_fp16(float* c, const uint32_t* a,
                                         uint32_t b0, uint32_t b1) {
  asm volatile(
      "mma.sync.aligned.m16n8k16.row.col.f32.f16.f16.f32 "
      "{%0,%1,%2,%3}, {%4,%5,%6,%7}, {%8,%9}, {%0,%1,%2,%3};"
      : "+f"(c[0]), "+f"(c[1]), "+f"(c[2]), "+f"(c[3])
      : "r"(a[0]), "r"(a[1]), "r"(a[2]), "r"(a[3]), "r"(b0), "r"(b1));
}

// ---------------------------------------------------------------------------
// Warp-tiled fp16 mma.sync GEMM, C[128x256] = A[128,K] * B[256,K]^T.
// Both operands K-major, single-pass fp16 with fp32 accumulation.
// 512 threads, 16 warps in 4x4; warp tile 32x64. 3-stage cp.async pipeline.
// mode 0: QKV proj (z=matrix)  mode 1: scores (z=batch)  mode 2: PV (z=batch)
// ---------------------------------------------------------------------------
constexpr int ASTG = 16384;   // 128 rows x 128B (BK = 64 fp16)
constexpr int BSTG = 32768;   // 256 rows x 128B
constexpr int STG = ASTG + BSTG;
constexpr int SMEM_DYN = 1024 + 3 * STG;  // 148480
constexpr float SCALE = 0.03125f;  // 1/sqrt(1024)

__global__ __launch_bounds__(512, 1) void gemm_tc(int mode, float* out) {
  extern __shared__ char dsm[];

  const int bx = blockIdx.x, by = blockIdx.y, bz = blockIdx.z;
  const int row0 = by * 128, col0 = bx * 256;

  const __half *ap, *bp;
  size_t lda, ldb;
  int nchunks;
  if (mode == 0) {
    ap = g_x16;
    bp = g_Wt16[bz];
    lda = D_; ldb = D_; nchunks = 16;
  } else if (mode == 1) {
    if (col0 > row0 + 127) return;  // tile fully above the diagonal
    size_t o = (size_t)bz * N_ * D_;
    ap = g_Q16 + o;
    bp = g_K16 + o;
    lda = D_; ldb = D_; nchunks = 16;
  } else {
    ap = g_P16 + (size_t)bz * N_ * N_;
    bp = g_Vt16[bz];
    lda = N_; ldb = N_; nchunks = (row0 + 128) / 64;  // causal K bound
  }

  const int tid = threadIdx.x;
  const int wid = tid >> 5, lid = tid & 31;
  const int wm = wid & 3, wn = wid >> 2;  // 4x4 warp grid; warp tile 32x64

  const uint32_t smA = (smem_u32(dsm) + 1023) & ~1023u;

  float acc[2][8][4];
#pragma unroll
  for (int i = 0; i < 2; ++i)
#pragma unroll
    for (int j = 0; j < 8; ++j)
#pragma unroll
      for (int k = 0; k < 4; ++k) acc[i][j][k] = 0.f;

  // ---- chunk loader: 512 threads; A 2x cp16, B 4x cp16 per thread ----
  auto load_chunk = [&](int c, int s) {
    const int k0 = c * 64;
    const uint32_t sa = smA + s * STG;
    const uint32_t sb = sa + ASTG;
    {  // A: 128 rows x 128B; thread t: row t>>2, quarter t&3
      const int r = tid >> 2, h = tid & 3;
      const uint32_t o0 = (uint32_t)(r * 128 + h * 32);
      const char* ag = (const char*)(ap + (size_t)(row0 + r) * lda + k0) + h * 32;
#pragma unroll
      for (int j = 0; j < 2; ++j)
        cp_async16(sa + swz128(o0 + j * 16), ag + j * 16);
    }
    {  // B: 256 rows x 128B; thread t: row t>>1, half t&1
      const int r = tid >> 1, h = tid & 1;
      const uint32_t o0 = (uint32_t)(r * 128 + h * 64);
      const char* bg = (const char*)(bp + (size_t)(col0 + r) * ldb + k0) + h * 64;
#pragma unroll
      for (int j = 0; j < 4; ++j)
        cp_async16(sb + swz128(o0 + j * 16), bg + j * 16);
    }
    CP_COMMIT();
  };

  load_chunk(0, 0);
  load_chunk(1, 1);

  for (int c = 0; c < nchunks; ++c) {
    if (c + 1 < nchunks)
      asm volatile("cp.async.wait_group 1;" ::: "memory");
    else
      asm volatile("cp.async.wait_group 0;" ::: "memory");
    __syncthreads();
    // stage (c+2)%3 is free: its previous reader (chunk c-1) finished
    // before the barrier above. Issue its loads, then compute chunk c.
    if (c + 2 < nchunks) load_chunk(c + 2, (c + 2) % 3);

    const uint32_t sa = smA + (c % 3) * STG;
    const uint32_t sb = sa + ASTG;

#pragma unroll
    for (int kk = 0; kk < 4; ++kk) {  // 4 x k16 per 64-wide chunk
      uint32_t af[2][4];
#pragma unroll
      for (int mt = 0; mt < 2; ++mt) {
        const int m0 = wm * 32 + mt * 16;
        const int row = m0 + ((lid >> 3) & 1) * 8 + (lid & 7);
        const int kb = kk * 32 + ((lid >> 4) & 1) * 16;
        ldmatrix_x4(af[mt][0], af[mt][1], af[mt][2], af[mt][3],
                    sa + row * 128 + (kb ^ ((row & 7) << 4)));
      }
      uint32_t bfr[4][4];
#pragma unroll
      for (int np = 0; np < 4; ++np) {
        const int n0 = wn * 64 + np * 16;
        const int row = n0 + ((lid >> 4) & 1) * 8 + (lid & 7);
        const int kb = kk * 32 + ((lid >> 3) & 1) * 16;
        ldmatrix_x4(bfr[np][0], bfr[np][1], bfr[np][2], bfr[np][3],
                    sb + row * 128 + (kb ^ ((row & 7) << 4)));
      }
#pragma unroll
      for (int mt = 0; mt < 2; ++mt)
#pragma unroll
        for (int nt = 0; nt < 8; ++nt)
          mma_fp16(acc[mt][nt], af[mt], bfr[nt >> 1][(nt & 1) * 2],
                   bfr[nt >> 1][(nt & 1) * 2 + 1]);
    }
    __syncthreads();
  }

  // ---- epilogue: fragment (c0,c1)=(m, n..n+1), (c2,c3)=(m+8, n..n+1) ----
#pragma unroll
  for (int mt = 0; mt < 2; ++mt) {
#pragma unroll
    for (int nt = 0; nt < 8; ++nt) {
      const int m = row0 + wm * 32 + mt * 16 + (lid >> 2);
      const int n = col0 + wn * 64 + nt * 8 + 2 * (lid & 3);
      const float* cf = acc[mt][nt];
      if (mode == 0) {
        __half* C = (bz == 0) ? g_Q16 : (bz == 1) ? g_K16 : g_V16;
#pragma unroll
        for (int hh = 0; hh < 2; ++hh) {
          const size_t o = (size_t)(m + hh * 8) * D_ + n;
          *(__half2*)(C + o) = __floats2half2_rn(cf[hh * 2], cf[hh * 2 + 1]);
        }
      } else if (mode == 1) {
#pragma unroll
        for (int hh = 0; hh < 2; ++hh) {
          float* sp = g_S + ((size_t)bz * N_ + m + hh * 8) * N_ + n;
          sp[0] = cf[hh * 2] * SCALE;
          sp[1] = cf[hh * 2 + 1] * SCALE;
        }
      } else {
#pragma unroll
        for (int hh = 0; hh < 2; ++hh) {
          float* op = out + ((size_t)bz * N_ + m + hh * 8) * D_ + n;
          op[0] = cf[hh * 2];
          op[1] = cf[hh * 2 + 1];
        }
      }
    }
  }
}

// ---------------------------------------------------------------------------
// Conversions
// ---------------------------------------------------------------------------
__global__ __launch_bounds__(256) void conv_x_kernel(const float* __restrict__ x) {
  size_t i = ((size_t)blockIdx.x * 256 + threadIdx.x) * 4;
  float4 v = *(const float4*)(x + i);
  __half2* o = (__half2*)(g_x16 + i);
  o[0] = __floats2half2_rn(v.x, v.y);
  o[1] = __floats2half2_rn(v.z, v.w);
}

// transpose-convert W[d][e] -> Wt16[e][d]
__global__ __launch_bounds__(256) void conv_w_kernel(const float* __restrict__ Wq,
                                                     const float* __restrict__ Wk,
                                                     const float* __restrict__ Wv) {
  const float* W = (blockIdx.z == 0) ? Wq : (blockIdx.z == 1) ? Wk : Wv;
  __half* T = g_Wt16[blockIdx.z];
  __shared__ float t[32][33];
  int tx = threadIdx.x & 31, ty = threadIdx.x >> 5;  // 32 x 8
  int d0 = blockIdx.y * 32, e0 = blockIdx.x * 32;
#pragma unroll
  for (int i = 0; i < 4; ++i)
    t[ty + i * 8][tx] = W[(size_t)(d0 + ty + i * 8) * D_ + e0 + tx];
  __syncthreads();
#pragma unroll
  for (int i = 0; i < 4; ++i)
    T[(size_t)(e0 + ty + i * 8) * D_ + d0 + tx] = __float2half_rn(t[tx][ty + i * 8]);
}

// transpose V16[b][tok][e] -> Vt16[b][e][tok]
__global__ __launch_bounds__(256) void conv_vt_kernel() {
  __shared__ uint16_t th[32][33];
  int tx = threadIdx.x & 31, ty = threadIdx.x >> 5;
  int tok0 = blockIdx.x * 32, e0 = blockIdx.y * 32, b = blockIdx.z;
  const uint16_t* Vh = (const uint16_t*)(g_V16) + (size_t)b * N_ * D_;
#pragma unroll
  for (int i = 0; i < 4; ++i)
    th[ty + i * 8][tx] = Vh[(size_t)(tok0 + ty + i * 8) * D_ + e0 + tx];
  __syncthreads();
  uint16_t* Oh = (uint16_t*)g_Vt16[b];
#pragma unroll
  for (int i = 0; i < 4; ++i)
    Oh[(size_t)(e0 + ty + i * 8) * N_ + tok0 + tx] = th[tx][ty + i * 8];
}

// ---------------------------------------------------------------------------
// Causal softmax: reads S fp32 (k <= q only), writes P fp16, zeros beyond
// ---------------------------------------------------------------------------
__global__ __launch_bounds__(256) void softmax_kernel() {
  const int q = blockIdx.x, b = blockIdx.y;
  const float* row = g_S + ((size_t)b * N_ + q) * N_;
  __half* ph = g_P16 + ((size_t)b * N_ + q) * N_;
  const int L = q + 1;
  const int tid = threadIdx.x;

  __shared__ float red[256];

  float m = -1e30f;
  for (int k = tid; k < L; k += 256) m = fmaxf(m, row[k]);
  red[tid] = m;
  __syncthreads();
  for (int s = 128; s > 0; s >>= 1) {
    if (tid < s) red[tid] = fmaxf(red[tid], red[tid + s]);
    __syncthreads();
  }
  m = red[0];
  __syncthreads();

  float sum = 0.f;
  for (int k = tid; k < L; k += 256) sum += expf(row[k] - m);
  red[tid] = sum;
  __syncthreads();
  for (int s = 128; s > 0; s >>= 1) {
    if (tid < s) red[tid] += red[tid + s];
    __syncthreads();
  }
  const float inv = 1.f / red[0];

  for (int k = tid; k < N_; k += 256) {
    float p = (k < L) ? expf(row[k] - m) * inv : 0.f;
    ph[k] = __float2half_rn(p);
  }
}

// ---------------------------------------------------------------------------
extern "C" void kernel_launch(void* const* d_in, const int* in_sizes, int n_in,
                              void* d_out, int out_size) {
  const float* x  = (const float*)d_in[0];
  const float* Wq = (const float*)d_in[1];
  const float* Wk = (const float*)d_in[2];
  const float* Wv = (const float*)d_in[3];
  float* out = (float*)d_out;

  cudaFuncSetAttribute(gemm_tc, cudaFuncAttributeMaxDynamicSharedMemorySize,
                       SMEM_DYN);

  // 1) convert inputs to fp16
  conv_x_kernel<<<(M_ * D_) / (256 * 4), 256>>>(x);
  conv_w_kernel<<<dim3(D_ / 32, D_ / 32, 3), 256>>>(Wq, Wk, Wv);
  // 2) QKV projections: C[8192,1024], 128x256 tiles
  gemm_tc<<<dim3(D_ / 256, M_ / 128, 3), 512, SMEM_DYN>>>(0, nullptr);
  // 3) transpose V for the PV GEMM
  conv_vt_kernel<<<dim3(N_ / 32, D_ / 32, B_), 256>>>();
  // 4) scores S = scale * Q K^T (tiles above the diagonal skipped)
  gemm_tc<<<dim3(N_ / 256, N_ / 128, B_), 512, SMEM_DYN>>>(1, nullptr);
  // 5) softmax -> P fp16
  softmax_kernel<<<dim3(N_, B_), 256>>>();
  // 6) O = P V (causally bounded K loop)
  gemm_tc<<<dim3(D_ / 256, N_ / 128, B_), 512, SMEM_DYN>>>(2, out);
}

// round 6
// speedup vs baseline: 2.8753x; 1.0536x over previous
#include <cuda_runtime.h>
#include <cuda_fp16.h>
#include <cstdint>

// ---------------------------------------------------------------------------
// Problem constants
// ---------------------------------------------------------------------------
constexpr int B_ = 4;
constexpr int N_ = 2048;
constexpr int D_ = 1024;
constexpr int M_ = B_ * N_;  // 8192 tokens

// ---------------------------------------------------------------------------
// Scratch (device globals — allocation is forbidden)
// ---------------------------------------------------------------------------
__device__ __half g_x16[M_ * D_];
__device__ __half g_Wt16[3][D_ * D_];       // W^T [e][d]
__device__ __half g_Q16[M_ * D_];
__device__ __half g_K16[M_ * D_];
__device__ __half g_V16[M_ * D_];
__device__ __half g_Vt16[B_][D_ * N_];      // V^T [e][tok]
__device__ float g_S[(size_t)B_ * N_ * N_];
__device__ __half g_P16[(size_t)B_ * N_ * N_];

// ---------------------------------------------------------------------------
// Helpers
// ---------------------------------------------------------------------------
__device__ __forceinline__ uint32_t smem_u32(const void* p) {
  uint32_t a;
  asm("{ .reg .u64 t; cvta.to.shared.u64 t, %1; cvt.u32.u64 %0, t; }"
      : "=r"(a) : "l"(p));
  return a;
}

__device__ __forceinline__ void cp_async16(uint32_t smem, const void* g) {
  asm volatile("cp.async.cg.shared.global [%0], [%1], 16;" ::"r"(smem), "l"(g)
               : "memory");
}
#define CP_COMMIT() asm volatile("cp.async.commit_group;" ::: "memory")

__device__ __forceinline__ uint32_t swz128(uint32_t off) {
  return off ^ ((off >> 3) & 0x70);
}

__device__ __forceinline__ void ldmatrix_x4(uint32_t& r0, uint32_t& r1,
                                            uint32_t& r2, uint32_t& r3,
                                            uint32_t addr) {
  asm volatile(
      "ldmatrix.sync.aligned.m8n8.x4.shared.b16 {%0,%1,%2,%3}, [%4];"
      : "=r"(r0), "=r"(r1), "=r"(r2), "=r"(r3)
      : "r"(addr));
}

__device__ __forceinline__ void mma_fp16(float* c, const uint32_t* a,
                                         uint32_t b0, uint32_t b1) {
  asm volatile(
      "mma.sync.aligned.m16n8k16.row.col.f32.f16.f16.f32 "
      "{%0,%1,%2,%3}, {%4,%5,%6,%7}, {%8,%9}, {%0,%1,%2,%3};"
      : "+f"(c[0]), "+f"(c[1]), "+f"(c[2]), "+f"(c[3])
      : "r"(a[0]), "r"(a[1]), "r"(a[2]), "r"(a[3]), "r"(b0), "r"(b1));
}

// ---------------------------------------------------------------------------
// Warp-tiled fp16 mma.sync GEMM, C[128x256] = A[128,K] * B[256,K]^T.
// Both operands K-major, single-pass fp16 with fp32 accumulation.
// 512 threads, 16 warps in 4x4; warp tile 32x64. 3-stage cp.async pipeline.
// mode 0: QKV proj (z=matrix)  mode 1: scores (z=batch)  mode 2: PV (z=batch)
// PV launches heavy tiles first (by reversed) for wave balance.
// ---------------------------------------------------------------------------
constexpr int ASTG = 16384;   // 128 rows x 128B (BK = 64 fp16)
constexpr int BSTG = 32768;   // 256 rows x 128B
constexpr int STG = ASTG + BSTG;
constexpr int SMEM_DYN = 1024 + 3 * STG;  // 148480
constexpr float SCALE = 0.03125f;  // 1/sqrt(1024)

__global__ __launch_bounds__(512, 1) void gemm_tc(int mode, float* out) {
  extern __shared__ char dsm[];

  const int bx = blockIdx.x, bz = blockIdx.z;
  // PV: reverse row-tile order so the heaviest (longest-K) tiles launch first.
  const int by = (mode == 2) ? (gridDim.y - 1 - blockIdx.y) : blockIdx.y;
  const int row0 = by * 128, col0 = bx * 256;

  const __half *ap, *bp;
  size_t lda, ldb;
  int nchunks;
  if (mode == 0) {
    ap = g_x16;
    bp = g_Wt16[bz];
    lda = D_; ldb = D_; nchunks = 16;
  } else if (mode == 1) {
    if (col0 > row0 + 127) return;  // tile fully above the diagonal
    size_t o = (size_t)bz * N_ * D_;
    ap = g_Q16 + o;
    bp = g_K16 + o;
    lda = D_; ldb = D_; nchunks = 16;
  } else {
    ap = g_P16 + (size_t)bz * N_ * N_;
    bp = g_Vt16[bz];
    lda = N_; ldb = N_; nchunks = (row0 + 128) / 64;  // causal K bound
  }

  const int tid = threadIdx.x;
  const int wid = tid >> 5, lid = tid & 31;
  const int wm = wid & 3, wn = wid >> 2;  // 4x4 warp grid; warp tile 32x64

  const uint32_t smA = (smem_u32(dsm) + 1023) & ~1023u;

  float acc[2][8][4];
#pragma unroll
  for (int i = 0; i < 2; ++i)
#pragma unroll
    for (int j = 0; j < 8; ++j)
#pragma unroll
      for (int k = 0; k < 4; ++k) acc[i][j][k] = 0.f;

  // ---- chunk loader: 512 threads; A 2x cp16, B 4x cp16 per thread ----
  auto load_chunk = [&](int c, int s) {
    const int k0 = c * 64;
    const uint32_t sa = smA + s * STG;
    const uint32_t sb = sa + ASTG;
    {  // A: 128 rows x 128B; thread t: row t>>2, quarter t&3
      const int r = tid >> 2, h = tid & 3;
      const uint32_t o0 = (uint32_t)(r * 128 + h * 32);
      const char* ag = (const char*)(ap + (size_t)(row0 + r) * lda + k0) + h * 32;
#pragma unroll
      for (int j = 0; j < 2; ++j)
        cp_async16(sa + swz128(o0 + j * 16), ag + j * 16);
    }
    {  // B: 256 rows x 128B; thread t: row t>>1, half t&1
      const int r = tid >> 1, h = tid & 1;
      const uint32_t o0 = (uint32_t)(r * 128 + h * 64);
      const char* bg = (const char*)(bp + (size_t)(col0 + r) * ldb + k0) + h * 64;
#pragma unroll
      for (int j = 0; j < 4; ++j)
        cp_async16(sb + swz128(o0 + j * 16), bg + j * 16);
    }
    CP_COMMIT();
  };

  load_chunk(0, 0);
  load_chunk(1, 1);

  for (int c = 0; c < nchunks; ++c) {
    if (c + 1 < nchunks)
      asm volatile("cp.async.wait_group 1;" ::: "memory");
    else
      asm volatile("cp.async.wait_group 0;" ::: "memory");
    __syncthreads();
    // stage (c+2)%3 is free: its previous reader (chunk c-1) finished
    // before the barrier above. Issue its loads, then compute chunk c.
    if (c + 2 < nchunks) load_chunk(c + 2, (c + 2) % 3);

    const uint32_t sa = smA + (c % 3) * STG;
    const uint32_t sb = sa + ASTG;

#pragma unroll
    for (int kk = 0; kk < 4; ++kk) {  // 4 x k16 per 64-wide chunk
      uint32_t af[2][4];
#pragma unroll
      for (int mt = 0; mt < 2; ++mt) {
        const int m0 = wm * 32 + mt * 16;
        const int row = m0 + ((lid >> 3) & 1) * 8 + (lid & 7);
        const int kb = kk * 32 + ((lid >> 4) & 1) * 16;
        ldmatrix_x4(af[mt][0], af[mt][1], af[mt][2], af[mt][3],
                    sa + row * 128 + (kb ^ ((row & 7) << 4)));
      }
      uint32_t bfr[4][4];
#pragma unroll
      for (int np = 0; np < 4; ++np) {
        const int n0 = wn * 64 + np * 16;
        const int row = n0 + ((lid >> 4) & 1) * 8 + (lid & 7);
        const int kb = kk * 32 + ((lid >> 3) & 1) * 16;
        ldmatrix_x4(bfr[np][0], bfr[np][1], bfr[np][2], bfr[np][3],
                    sb + row * 128 + (kb ^ ((row & 7) << 4)));
      }
#pragma unroll
      for (int mt = 0; mt < 2; ++mt)
#pragma unroll
        for (int nt = 0; nt < 8; ++nt)
          mma_fp16(acc[mt][nt], af[mt], bfr[nt >> 1][(nt & 1) * 2],
                   bfr[nt >> 1][(nt & 1) * 2 + 1]);
    }
    __syncthreads();
  }

  // ---- epilogue: fragment (c0,c1)=(m, n..n+1), (c2,c3)=(m+8, n..n+1) ----
#pragma unroll
  for (int mt = 0; mt < 2; ++mt) {
#pragma unroll
    for (int nt = 0; nt < 8; ++nt) {
      const int m = row0 + wm * 32 + mt * 16 + (lid >> 2);
      const int n = col0 + wn * 64 + nt * 8 + 2 * (lid & 3);
      const float* cf = acc[mt][nt];
      if (mode == 0) {
        __half* C = (bz == 0) ? g_Q16 : (bz == 1) ? g_K16 : g_V16;
#pragma unroll
        for (int hh = 0; hh < 2; ++hh) {
          const size_t o = (size_t)(m + hh * 8) * D_ + n;
          *(__half2*)(C + o) = __floats2half2_rn(cf[hh * 2], cf[hh * 2 + 1]);
        }
      } else if (mode == 1) {
#pragma unroll
        for (int hh = 0; hh < 2; ++hh) {
          float* sp = g_S + ((size_t)bz * N_ + m + hh * 8) * N_ + n;
          sp[0] = cf[hh * 2] * SCALE;
          sp[1] = cf[hh * 2 + 1] * SCALE;
        }
      } else {
#pragma unroll
        for (int hh = 0; hh < 2; ++hh) {
          float* op = out + ((size_t)bz * N_ + m + hh * 8) * D_ + n;
          op[0] = cf[hh * 2];
          op[1] = cf[hh * 2 + 1];
        }
      }
    }
  }
}

// ---------------------------------------------------------------------------
// Conversions
// ---------------------------------------------------------------------------
__global__ __launch_bounds__(256) void conv_x_kernel(const float* __restrict__ x) {
  size_t i = ((size_t)blockIdx.x * 256 + threadIdx.x) * 4;
  float4 v = *(const float4*)(x + i);
  __half2* o = (__half2*)(g_x16 + i);
  o[0] = __floats2half2_rn(v.x, v.y);
  o[1] = __floats2half2_rn(v.z, v.w);
}

// transpose-convert W[d][e] -> Wt16[e][d]
__global__ __launch_bounds__(256) void conv_w_kernel(const float* __restrict__ Wq,
                                                     const float* __restrict__ Wk,
                                                     const float* __restrict__ Wv) {
  const float* W = (blockIdx.z == 0) ? Wq : (blockIdx.z == 1) ? Wk : Wv;
  __half* T = g_Wt16[blockIdx.z];
  __shared__ float t[32][33];
  int tx = threadIdx.x & 31, ty = threadIdx.x >> 5;  // 32 x 8
  int d0 = blockIdx.y * 32, e0 = blockIdx.x * 32;
#pragma unroll
  for (int i = 0; i < 4; ++i)
    t[ty + i * 8][tx] = W[(size_t)(d0 + ty + i * 8) * D_ + e0 + tx];
  __syncthreads();
#pragma unroll
  for (int i = 0; i < 4; ++i)
    T[(size_t)(e0 + ty + i * 8) * D_ + d0 + tx] = __float2half_rn(t[tx][ty + i * 8]);
}

// transpose V16[b][tok][e] -> Vt16[b][e][tok]
__global__ __launch_bounds__(256) void conv_vt_kernel() {
  __shared__ uint16_t th[32][33];
  int tx = threadIdx.x & 31, ty = threadIdx.x >> 5;
  int tok0 = blockIdx.x * 32, e0 = blockIdx.y * 32, b = blockIdx.z;
  const uint16_t* Vh = (const uint16_t*)(g_V16) + (size_t)b * N_ * D_;
#pragma unroll
  for (int i = 0; i < 4; ++i)
    th[ty + i * 8][tx] = Vh[(size_t)(tok0 + ty + i * 8) * D_ + e0 + tx];
  __syncthreads();
  uint16_t* Oh = (uint16_t*)g_Vt16[b];
#pragma unroll
  for (int i = 0; i < 4; ++i)
    Oh[(size_t)(e0 + ty + i * 8) * N_ + tok0 + tx] = th[tx][ty + i * 8];
}

// ---------------------------------------------------------------------------
// Causal softmax, single gmem pass: row cached in smem, shuffle reductions.
// Writes P fp16 with zeros up to the 128-aligned causal tile bound (what the
// PV GEMM actually reads).
// ---------------------------------------------------------------------------
__global__ __launch_bounds__(256) void softmax_kernel() {
  const int q = blockIdx.x, b = blockIdx.y;
  const float* row = g_S + ((size_t)b * N_ + q) * N_;
  __half* ph = g_P16 + ((size_t)b * N_ + q) * N_;
  const int L = q + 1;
  const int wlim = ((q >> 7) + 1) << 7;  // PV reads cols [0, wlim)
  const int tid = threadIdx.x;

  __shared__ float buf[N_];
  __shared__ float redm[8], reds[8];

  // pass 1: load row -> smem, local max
  float m = -1e30f;
  for (int k = tid; k < L; k += 256) {
    float v = row[k];
    buf[k] = v;
    m = fmaxf(m, v);
  }
#pragma unroll
  for (int o = 16; o; o >>= 1) m = fmaxf(m, __shfl_xor_sync(~0u, m, o));
  if ((tid & 31) == 0) redm[tid >> 5] = m;
  __syncthreads();
  float m0 = redm[0];
#pragma unroll
  for (int w = 1; w < 8; ++w) m0 = fmaxf(m0, redm[w]);

  // pass 2 (smem): exp and local sum
  float sum = 0.f;
  const float c = 1.44269504f;
  for (int k = tid; k < L; k += 256) {
    float e = exp2f((buf[k] - m0) * c);
    buf[k] = e;
    sum += e;
  }
#pragma unroll
  for (int o = 16; o; o >>= 1) sum += __shfl_xor_sync(~0u, sum, o);
  if ((tid & 31) == 0) reds[tid >> 5] = sum;
  __syncthreads();
  float s0 = 0.f;
#pragma unroll
  for (int w = 0; w < 8; ++w) s0 += reds[w];
  const float inv = 1.f / s0;

  // pass 3 (smem): normalize and store fp16 (+ zero pad to tile bound)
  for (int k = tid; k < wlim; k += 256)
    ph[k] = __float2half_rn(k < L ? buf[k] * inv : 0.f);
}

// ---------------------------------------------------------------------------
extern "C" void kernel_launch(void* const* d_in, const int* in_sizes, int n_in,
                              void* d_out, int out_size) {
  const float* x  = (const float*)d_in[0];
  const float* Wq = (const float*)d_in[1];
  const float* Wk = (const float*)d_in[2];
  const float* Wv = (const float*)d_in[3];
  float* out = (float*)d_out;

  cudaFuncSetAttribute(gemm_tc, cudaFuncAttributeMaxDynamicSharedMemorySize,
                       SMEM_DYN);

  // 1) convert inputs to fp16
  conv_x_kernel<<<(M_ * D_) / (256 * 4), 256>>>(x);
  conv_w_kernel<<<dim3(D_ / 32, D_ / 32, 3), 256>>>(Wq, Wk, Wv);
  // 2) QKV projections: C[8192,1024], 128x256 tiles
  gemm_tc<<<dim3(D_ / 256, M_ / 128, 3), 512, SMEM_DYN>>>(0, nullptr);
  // 3) transpose V for the PV GEMM
  conv_vt_kernel<<<dim3(N_ / 32, D_ / 32, B_), 256>>>();
  // 4) scores S = scale * Q K^T (tiles above the diagonal skipped)
  gemm_tc<<<dim3(N_ / 256, N_ / 128, B_), 512, SMEM_DYN>>>(1, nullptr);
  // 5) softmax -> P fp16
  softmax_kernel<<<dim3(N_, B_), 256>>>();
  // 6) O = P V (causally bounded K loop, heavy tiles first)
  gemm_tc<<<dim3(D_ / 256, N_ / 128, B_), 512, SMEM_DYN>>>(2, out);
}

// round 7
// speedup vs baseline: 3.0139x; 1.0482x over previous
#include <cuda_runtime.h>
#include <cuda_fp16.h>
#include <cstdint>

// ---------------------------------------------------------------------------
// Problem constants
// ---------------------------------------------------------------------------
constexpr int B_ = 4;
constexpr int N_ = 2048;
constexpr int D_ = 1024;
constexpr int M_ = B_ * N_;  // 8192 tokens

// ---------------------------------------------------------------------------
// Scratch (device globals — allocation is forbidden)
// ---------------------------------------------------------------------------
__device__ __half g_x16[M_ * D_];
__device__ __half g_Wt16[3][D_ * D_];       // W^T [e][d]
__device__ __half g_Q16[M_ * D_];
__device__ __half g_K16[M_ * D_];
__device__ __half g_V16[M_ * D_];
__device__ __half g_Vt16[B_][D_ * N_];      // V^T [e][tok]
__device__ float g_S[(size_t)B_ * N_ * N_];
__device__ __half g_P16[(size_t)B_ * N_ * N_];

// ---------------------------------------------------------------------------
// Helpers
// ---------------------------------------------------------------------------
__device__ __forceinline__ uint32_t smem_u32(const void* p) {
  uint32_t a;
  asm("{ .reg .u64 t; cvta.to.shared.u64 t, %1; cvt.u32.u64 %0, t; }"
      : "=r"(a) : "l"(p));
  return a;
}

__device__ __forceinline__ void cp_async16(uint32_t smem, const void* g) {
  asm volatile("cp.async.cg.shared.global [%0], [%1], 16;" ::"r"(smem), "l"(g)
               : "memory");
}
#define CP_COMMIT() asm volatile("cp.async.commit_group;" ::: "memory")

__device__ __forceinline__ uint32_t swz128(uint32_t off) {
  return off ^ ((off >> 3) & 0x70);
}

__device__ __forceinline__ void ldmatrix_x4(uint32_t& r0, uint32_t& r1,
                                            uint32_t& r2, uint32_t& r3,
                                            uint32_t addr) {
  asm volatile(
      "ldmatrix.sync.aligned.m8n8.x4.shared.b16 {%0,%1,%2,%3}, [%4];"
      : "=r"(r0), "=r"(r1), "=r"(r2), "=r"(r3)
      : "r"(addr));
}

__device__ __forceinline__ void mma_fp16(float* c, const uint32_t* a,
                                         uint32_t b0, uint32_t b1) {
  asm volatile(
      "mma.sync.aligned.m16n8k16.row.col.f32.f16.f16.f32 "
      "{%0,%1,%2,%3}, {%4,%5,%6,%7}, {%8,%9}, {%0,%1,%2,%3};"
      : "+f"(c[0]), "+f"(c[1]), "+f"(c[2]), "+f"(c[3])
      : "r"(a[0]), "r"(a[1]), "r"(a[2]), "r"(a[3]), "r"(b0), "r"(b1));
}

// ---------------------------------------------------------------------------
// Warp-tiled fp16 mma.sync GEMM, C[128x256] = A[128,K] * B[256,K]^T.
// Both operands K-major, single-pass fp16 with fp32 accumulation.
// 512 threads, 16 warps in 4x4; warp tile 32x64.
// Pipeline: 2 stages x 128-wide K steps (two 64-K panels per step),
// single __syncthreads per step.
// mode 0: QKV proj (z=matrix)  mode 1: scores (z=batch)  mode 2: PV (z=batch)
// PV launches heavy tiles first (by reversed) for wave balance.
// ---------------------------------------------------------------------------
constexpr int ASTG = 16384;        // 128 rows x 128B (one 64-K panel of A)
constexpr int BSTG = 32768;        // 256 rows x 128B
constexpr int PANEL = ASTG + BSTG; // 48 KB
constexpr int STEP = 2 * PANEL;    // 96 KB: K=128 per pipeline step
constexpr int SMEM_DYN = 1024 + 2 * STEP;  // 197632
constexpr float SCALE = 0.03125f;  // 1/sqrt(1024)

__global__ __launch_bounds__(512, 1) void gemm_tc(int mode, float* out) {
  extern __shared__ char dsm[];

  const int bx = blockIdx.x, bz = blockIdx.z;
  // PV: reverse row-tile order so the heaviest (longest-K) tiles launch first.
  const int by = (mode == 2) ? (gridDim.y - 1 - blockIdx.y) : blockIdx.y;
  const int row0 = by * 128, col0 = bx * 256;

  const __half *ap, *bp;
  size_t lda, ldb;
  int nsteps;
  if (mode == 0) {
    ap = g_x16;
    bp = g_Wt16[bz];
    lda = D_; ldb = D_; nsteps = 8;
  } else if (mode == 1) {
    if (col0 > row0 + 127) return;  // tile fully above the diagonal
    size_t o = (size_t)bz * N_ * D_;
    ap = g_Q16 + o;
    bp = g_K16 + o;
    lda = D_; ldb = D_; nsteps = 8;
  } else {
    ap = g_P16 + (size_t)bz * N_ * N_;
    bp = g_Vt16[bz];
    lda = N_; ldb = N_; nsteps = by + 1;  // causal K bound (K = 128*(by+1))
  }

  const int tid = threadIdx.x;
  const int wid = tid >> 5, lid = tid & 31;
  const int wm = wid & 3, wn = wid >> 2;  // 4x4 warp grid; warp tile 32x64

  const uint32_t smA = (smem_u32(dsm) + 1023) & ~1023u;

  float acc[2][8][4];
#pragma unroll
  for (int i = 0; i < 2; ++i)
#pragma unroll
    for (int j = 0; j < 8; ++j)
#pragma unroll
      for (int k = 0; k < 4; ++k) acc[i][j][k] = 0.f;

  // ---- 64-K panel loader: 512 threads; A 2x cp16, B 4x cp16 per thread ----
  auto load_panel = [&](int c64, uint32_t sbase) {
    const int k0 = c64 * 64;
    const uint32_t sa = sbase;
    const uint32_t sb = sbase + ASTG;
    {  // A: 128 rows x 128B; thread t: row t>>2, quarter t&3
      const int r = tid >> 2, h = tid & 3;
      const uint32_t o0 = (uint32_t)(r * 128 + h * 32);
      const char* ag = (const char*)(ap + (size_t)(row0 + r) * lda + k0) + h * 32;
#pragma unroll
      for (int j = 0; j < 2; ++j)
        cp_async16(sa + swz128(o0 + j * 16), ag + j * 16);
    }
    {  // B: 256 rows x 128B; thread t: row t>>1, half t&1
      const int r = tid >> 1, h = tid & 1;
      const uint32_t o0 = (uint32_t)(r * 128 + h * 64);
      const char* bg = (const char*)(bp + (size_t)(col0 + r) * ldb + k0) + h * 64;
#pragma unroll
      for (int j = 0; j < 4; ++j)
        cp_async16(sb + swz128(o0 + j * 16), bg + j * 16);
    }
  };
  auto load_step = [&](int cs, int s) {
    load_panel(2 * cs, smA + s * STEP);
    load_panel(2 * cs + 1, smA + s * STEP + PANEL);
    CP_COMMIT();
  };

  load_step(0, 0);

  for (int c = 0; c < nsteps; ++c) {
    asm volatile("cp.async.wait_group 0;" ::: "memory");
    __syncthreads();
    // This barrier also orders step c-1's compute (stage (c+1)&1 readers)
    // before the writes below — no trailing barrier needed.
    if (c + 1 < nsteps) load_step(c + 1, (c + 1) & 1);

    const uint32_t sbase = smA + (c & 1) * STEP;

#pragma unroll
    for (int kk2 = 0; kk2 < 8; ++kk2) {  // 8 x k16 per 128-wide step
      const uint32_t sa = sbase + (kk2 >> 2) * PANEL;
      const uint32_t sb = sa + ASTG;
      const int kk = kk2 & 3;

      uint32_t af[2][4];
#pragma unroll
      for (int mt = 0; mt < 2; ++mt) {
        const int m0 = wm * 32 + mt * 16;
        const int row = m0 + ((lid >> 3) & 1) * 8 + (lid & 7);
        const int kb = kk * 32 + ((lid >> 4) & 1) * 16;
        ldmatrix_x4(af[mt][0], af[mt][1], af[mt][2], af[mt][3],
                    sa + row * 128 + (kb ^ ((row & 7) << 4)));
      }
      uint32_t bfr[4][4];
#pragma unroll
      for (int np = 0; np < 4; ++np) {
        const int n0 = wn * 64 + np * 16;
        const int row = n0 + ((lid >> 4) & 1) * 8 + (lid & 7);
        const int kb = kk * 32 + ((lid >> 3) & 1) * 16;
        ldmatrix_x4(bfr[np][0], bfr[np][1], bfr[np][2], bfr[np][3],
                    sb + row * 128 + (kb ^ ((row & 7) << 4)));
      }
#pragma unroll
      for (int mt = 0; mt < 2; ++mt)
#pragma unroll
        for (int nt = 0; nt < 8; ++nt)
          mma_fp16(acc[mt][nt], af[mt], bfr[nt >> 1][(nt & 1) * 2],
                   bfr[nt >> 1][(nt & 1) * 2 + 1]);
    }
  }

  // ---- epilogue: fragment (c0,c1)=(m, n..n+1), (c2,c3)=(m+8, n..n+1) ----
#pragma unroll
  for (int mt = 0; mt < 2; ++mt) {
#pragma unroll
    for (int nt = 0; nt < 8; ++nt) {
      const int m = row0 + wm * 32 + mt * 16 + (lid >> 2);
      const int n = col0 + wn * 64 + nt * 8 + 2 * (lid & 3);
      const float* cf = acc[mt][nt];
      if (mode == 0) {
        __half* C = (bz == 0) ? g_Q16 : (bz == 1) ? g_K16 : g_V16;
#pragma unroll
        for (int hh = 0; hh < 2; ++hh) {
          const size_t o = (size_t)(m + hh * 8) * D_ + n;
          *(__half2*)(C + o) = __floats2half2_rn(cf[hh * 2], cf[hh * 2 + 1]);
        }
      } else if (mode == 1) {
#pragma unroll
        for (int hh = 0; hh < 2; ++hh) {
          float* sp = g_S + ((size_t)bz * N_ + m + hh * 8) * N_ + n;
          sp[0] = cf[hh * 2] * SCALE;
          sp[1] = cf[hh * 2 + 1] * SCALE;
        }
      } else {
#pragma unroll
        for (int hh = 0; hh < 2; ++hh) {
          float* op = out + ((size_t)bz * N_ + m + hh * 8) * D_ + n;
          op[0] = cf[hh * 2];
          op[1] = cf[hh * 2 + 1];
        }
      }
    }
  }
}

// ---------------------------------------------------------------------------
// Conversions
// ---------------------------------------------------------------------------
__global__ __launch_bounds__(256) void conv_x_kernel(const float* __restrict__ x) {
  size_t i = ((size_t)blockIdx.x * 256 + threadIdx.x) * 4;
  float4 v = *(const float4*)(x + i);
  __half2* o = (__half2*)(g_x16 + i);
  o[0] = __floats2half2_rn(v.x, v.y);
  o[1] = __floats2half2_rn(v.z, v.w);
}

// transpose-convert W[d][e] -> Wt16[e][d]
__global__ __launch_bounds__(256) void conv_w_kernel(const float* __restrict__ Wq,
                                                     const float* __restrict__ Wk,
                                                     const float* __restrict__ Wv) {
  const float* W = (blockIdx.z == 0) ? Wq : (blockIdx.z == 1) ? Wk : Wv;
  __half* T = g_Wt16[blockIdx.z];
  __shared__ float t[32][33];
  int tx = threadIdx.x & 31, ty = threadIdx.x >> 5;  // 32 x 8
  int d0 = blockIdx.y * 32, e0 = blockIdx.x * 32;
#pragma unroll
  for (int i = 0; i < 4; ++i)
    t[ty + i * 8][tx] = W[(size_t)(d0 + ty + i * 8) * D_ + e0 + tx];
  __syncthreads();
#pragma unroll
  for (int i = 0; i < 4; ++i)
    T[(size_t)(e0 + ty + i * 8) * D_ + d0 + tx] = __float2half_rn(t[tx][ty + i * 8]);
}

// transpose V16[b][tok][e] -> Vt16[b][e][tok]
__global__ __launch_bounds__(256) void conv_vt_kernel() {
  __shared__ uint16_t th[32][33];
  int tx = threadIdx.x & 31, ty = threadIdx.x >> 5;
  int tok0 = blockIdx.x * 32, e0 = blockIdx.y * 32, b = blockIdx.z;
  const uint16_t* Vh = (const uint16_t*)(g_V16) + (size_t)b * N_ * D_;
#pragma unroll
  for (int i = 0; i < 4; ++i)
    th[ty + i * 8][tx] = Vh[(size_t)(tok0 + ty + i * 8) * D_ + e0 + tx];
  __syncthreads();
  uint16_t* Oh = (uint16_t*)g_Vt16[b];
#pragma unroll
  for (int i = 0; i < 4; ++i)
    Oh[(size_t)(e0 + ty + i * 8) * N_ + tok0 + tx] = th[tx][ty + i * 8];
}

// ---------------------------------------------------------------------------
// Causal softmax, single gmem pass: row cached in smem, shuffle reductions.
// Writes P fp16 with zeros up to the 128-aligned causal tile bound (what the
// PV GEMM actually reads).
// ---------------------------------------------------------------------------
__global__ __launch_bounds__(256) void softmax_kernel() {
  const int q = blockIdx.x, b = blockIdx.y;
  const float* row = g_S + ((size_t)b * N_ + q) * N_;
  __half* ph = g_P16 + ((size_t)b * N_ + q) * N_;
  const int L = q + 1;
  const int wlim = ((q >> 7) + 1) << 7;  // PV reads cols [0, wlim)
  const int tid = threadIdx.x;

  __shared__ float buf[N_];
  __shared__ float redm[8], reds[8];

  // pass 1: load row -> smem, local max
  float m = -1e30f;
  for (int k = tid; k < L; k += 256) {
    float v = row[k];
    buf[k] = v;
    m = fmaxf(m, v);
  }
#pragma unroll
  for (int o = 16; o; o >>= 1) m = fmaxf(m, __shfl_xor_sync(~0u, m, o));
  if ((tid & 31) == 0) redm[tid >> 5] = m;
  __syncthreads();
  float m0 = redm[0];
#pragma unroll
  for (int w = 1; w < 8; ++w) m0 = fmaxf(m0, redm[w]);

  // pass 2 (smem): exp and local sum
  float sum = 0.f;
  const float c = 1.44269504f;
  for (int k = tid; k < L; k += 256) {
    float e = exp2f((buf[k] - m0) * c);
    buf[k] = e;
    sum += e;
  }
#pragma unroll
  for (int o = 16; o; o >>= 1) sum += __shfl_xor_sync(~0u, sum, o);
  if ((tid & 31) == 0) reds[tid >> 5] = sum;
  __syncthreads();
  float s0 = 0.f;
#pragma unroll
  for (int w = 0; w < 8; ++w) s0 += reds[w];
  const float inv = 1.f / s0;

  // pass 3 (smem): normalize and store fp16 (+ zero pad to tile bound)
  for (int k = tid; k < wlim; k += 256)
    ph[k] = __float2half_rn(k < L ? buf[k] * inv : 0.f);
}

// ---------------------------------------------------------------------------
extern "C" void kernel_launch(void* const* d_in, const int* in_sizes, int n_in,
                              void* d_out, int out_size) {
  const float* x  = (const float*)d_in[0];
  const float* Wq = (const float*)d_in[1];
  const float* Wk = (const float*)d_in[2];
  const float* Wv = (const float*)d_in[3];
  float* out = (float*)d_out;

  cudaFuncSetAttribute(gemm_tc, cudaFuncAttributeMaxDynamicSharedMemorySize,
                       SMEM_DYN);

  // 1) convert inputs to fp16
  conv_x_kernel<<<(M_ * D_) / (256 * 4), 256>>>(x);
  conv_w_kernel<<<dim3(D_ / 32, D_ / 32, 3), 256>>>(Wq, Wk, Wv);
  // 2) QKV projections: C[8192,1024], 128x256 tiles
  gemm_tc<<<dim3(D_ / 256, M_ / 128, 3), 512, SMEM_DYN>>>(0, nullptr);
  // 3) transpose V for the PV GEMM
  conv_vt_kernel<<<dim3(N_ / 32, D_ / 32, B_), 256>>>();
  // 4) scores S = scale * Q K^T (tiles above the diagonal skipped)
  gemm_tc<<<dim3(N_ / 256, N_ / 128, B_), 512, SMEM_DYN>>>(1, nullptr);
  // 5) softmax -> P fp16
  softmax_kernel<<<dim3(N_, B_), 256>>>();
  // 6) O = P V (causally bounded K loop, heavy tiles first)
  gemm_tc<<<dim3(D_ / 256, N_ / 128, B_), 512, SMEM_DYN>>>(2, out);
}

// round 9
// speedup vs baseline: 3.0967x; 1.0275x over previous
#include <cuda_runtime.h>
#include <cuda_fp16.h>
#include <cstdint>

// ---------------------------------------------------------------------------
// Problem constants
// ---------------------------------------------------------------------------
constexpr int B_ = 4;
constexpr int N_ = 2048;
constexpr int D_ = 1024;
constexpr int M_ = B_ * N_;  // 8192 tokens

// ---------------------------------------------------------------------------
// Scratch (device globals — allocation is forbidden)
// ---------------------------------------------------------------------------
__device__ __half g_x16[M_ * D_];
__device__ __half g_Wt16[3][D_ * D_];       // W^T [e][d]
__device__ __half g_Q16[M_ * D_];
__device__ __half g_K16[M_ * D_];
__device__ __half g_V16[M_ * D_];
__device__ float g_S[(size_t)B_ * N_ * N_];
__device__ __half g_P16[(size_t)B_ * N_ * N_];

// ---------------------------------------------------------------------------
// Helpers
// ---------------------------------------------------------------------------
__device__ __forceinline__ uint32_t smem_u32(const void* p) {
  uint32_t a;
  asm("{ .reg .u64 t; cvta.to.shared.u64 t, %1; cvt.u32.u64 %0, t; }"
      : "=r"(a) : "l"(p));
  return a;
}

__device__ __forceinline__ void cp_async16(uint32_t smem, const void* g) {
  asm volatile("cp.async.cg.shared.global [%0], [%1], 16;" ::"r"(smem), "l"(g)
               : "memory");
}
#define CP_COMMIT() asm volatile("cp.async.commit_group;" ::: "memory")

__device__ __forceinline__ uint32_t swz128(uint32_t off) {  // 128B rows
  return off ^ ((off >> 3) & 0x70);
}
__device__ __forceinline__ uint32_t swz256(uint32_t off) {  // 256B rows
  return off ^ (((off >> 8) & 7) << 4);
}

__device__ __forceinline__ void ldmatrix_x4(uint32_t& r0, uint32_t& r1,
                                            uint32_t& r2, uint32_t& r3,
                                            uint32_t addr) {
  asm volatile(
      "ldmatrix.sync.aligned.m8n8.x4.shared.b16 {%0,%1,%2,%3}, [%4];"
      : "=r"(r0), "=r"(r1), "=r"(r2), "=r"(r3)
      : "r"(addr));
}

__device__ __forceinline__ void ldmatrix_x4_trans(uint32_t& r0, uint32_t& r1,
                                                  uint32_t& r2, uint32_t& r3,
                                                  uint32_t addr) {
  asm volatile(
      "ldmatrix.sync.aligned.m8n8.x4.trans.shared.b16 {%0,%1,%2,%3}, [%4];"
      : "=r"(r0), "=r"(r1), "=r"(r2), "=r"(r3)
      : "r"(addr));
}

__device__ __forceinline__ void mma_fp16(float* c, const uint32_t* a,
                                         uint32_t b0, uint32_t b1) {
  asm volatile(
      "mma.sync.aligned.m16n8k16.row.col.f32.f16.f16.f32 "
      "{%0,%1,%2,%3}, {%4,%5,%6,%7}, {%8,%9}, {%0,%1,%2,%3};"
      : "+f"(c[0]), "+f"(c[1]), "+f"(c[2]), "+f"(c[3])
      : "r"(a[0]), "r"(a[1]), "r"(a[2]), "r"(a[3]), "r"(b0), "r"(b1));
}

// ---------------------------------------------------------------------------
// Warp-tiled fp16 mma.sync GEMM, C[128x128], fp32 accumulation.
// 256 threads, 8 warps (4x2), warp tile 32x64. 2-stage BK=64 pipeline,
// single __syncthreads per step, occupancy 2 CTAs/SM.
// MODE 0: QKV proj  (A=x K-major,  B=W^T K-major rows)
// MODE 1: scores    (A=Q K-major,  B=K  K-major rows; causal tile skip)
// MODE 2: PV        (A=P K-major,  B=V natural [tok][e] + ldmatrix.trans;
//                    causal K bound; heavy tiles first)
// ---------------------------------------------------------------------------
constexpr int ASTG = 16384;        // 128 rows x 128B
constexpr int BSTG = 16384;        // mode01: 128 n-rows x 128B; mode2: 64 k-rows x 256B
constexpr int STG = ASTG + BSTG;   // 32 KB per stage
constexpr int SMEM_DYN = 1024 + 2 * STG;  // 66560
constexpr float SCALE = 0.03125f;  // 1/sqrt(1024)

template <int MODE>
__global__ __launch_bounds__(256, 2) void gemm_tc(float* out) {
  extern __shared__ char dsm[];

  const int bx = blockIdx.x, bz = blockIdx.z;
  const int by = (MODE == 2) ? (gridDim.y - 1 - blockIdx.y) : blockIdx.y;
  const int row0 = by * 128, col0 = bx * 128;

  const __half *ap, *bp;
  size_t lda;
  int nsteps;
  if constexpr (MODE == 0) {
    ap = g_x16;
    bp = g_Wt16[bz];
    lda = D_; nsteps = 16;
  } else if constexpr (MODE == 1) {
    if (bx > by) return;  // tile fully above the diagonal
    size_t o = (size_t)bz * N_ * D_;
    ap = g_Q16 + o;
    bp = g_K16 + o;
    lda = D_; nsteps = 16;
  } else {
    ap = g_P16 + (size_t)bz * N_ * N_;
    bp = g_V16 + (size_t)bz * N_ * D_;
    lda = N_; nsteps = 2 * (by + 1);  // causal: K = 128*(by+1), BK=64
  }

  const int tid = threadIdx.x;
  const int wid = tid >> 5, lid = tid & 31;
  const int wm = wid & 3, wn = wid >> 2;  // 4x2 warp grid; warp tile 32x64

  const uint32_t smA = (smem_u32(dsm) + 1023) & ~1023u;

  float acc[2][8][4];
#pragma unroll
  for (int i = 0; i < 2; ++i)
#pragma unroll
    for (int j = 0; j < 8; ++j)
#pragma unroll
      for (int k = 0; k < 4; ++k) acc[i][j][k] = 0.f;

  // ---- step loader (BK=64): 256 threads, A 4x cp16 + B 4x cp16 each ----
  auto load_step = [&](int c, int s) {
    const int k0 = c * 64;
    const uint32_t sa = smA + s * STG;
    const uint32_t sb = sa + ASTG;
    {  // A: 128 rows x 128B; thread t: row t>>1, half t&1
      const int r = tid >> 1, h = tid & 1;
      const uint32_t o0 = (uint32_t)(r * 128 + h * 64);
      const char* ag = (const char*)(ap + (size_t)(row0 + r) * lda + k0) + h * 64;
#pragma unroll
      for (int j = 0; j < 4; ++j)
        cp_async16(sa + swz128(o0 + j * 16), ag + j * 16);
    }
    if constexpr (MODE != 2) {
      // B: 128 n-rows x 128B K-major; thread t: row t>>1, half t&1
      const int r = tid >> 1, h = tid & 1;
      const uint32_t o0 = (uint32_t)(r * 128 + h * 64);
      const char* bg = (const char*)(bp + (size_t)(col0 + r) * lda + k0) + h * 64;
#pragma unroll
      for (int j = 0; j < 4; ++j)
        cp_async16(sb + swz128(o0 + j * 16), bg + j * 16);
    } else {
      // B: V natural layout, 64 k-rows x 256B (128 e cols)
      const int r = tid >> 2, seg = tid & 3;
      const uint32_t o0 = (uint32_t)(r * 256 + seg * 64);
      const char* bg = (const char*)(bp + (size_t)(k0 + r) * D_ + col0 + seg * 32);
#pragma unroll
      for (int j = 0; j < 4; ++j)
        cp_async16(sb + swz256(o0 + j * 16), bg + j * 16);
    }
    CP_COMMIT();
  };

  load_step(0, 0);

  for (int c = 0; c < nsteps; ++c) {
    asm volatile("cp.async.wait_group 0;" ::: "memory");
    __syncthreads();
    // Barrier also orders step c-1's compute (other-stage readers) before
    // the writes below — no trailing barrier needed.
    if (c + 1 < nsteps) load_step(c + 1, (c + 1) & 1);

    const uint32_t sa = smA + (c & 1) * STG;
    const uint32_t sb = sa + ASTG;

#pragma unroll
    for (int kk = 0; kk < 4; ++kk) {  // 4 x k16 per 64-wide step
      uint32_t af[2][4];
#pragma unroll
      for (int mt = 0; mt < 2; ++mt) {
        const int m0 = wm * 32 + mt * 16;
        const int row = m0 + ((lid >> 3) & 1) * 8 + (lid & 7);
        const int kb = kk * 32 + ((lid >> 4) & 1) * 16;
        ldmatrix_x4(af[mt][0], af[mt][1], af[mt][2], af[mt][3],
                    sa + row * 128 + (kb ^ ((row & 7) << 4)));
      }
      uint32_t bfr[4][4];
#pragma unroll
      for (int np = 0; np < 4; ++np) {
        if constexpr (MODE != 2) {
          const int n0 = wn * 64 + np * 16;
          const int row = n0 + ((lid >> 4) & 1) * 8 + (lid & 7);
          const int kb = kk * 32 + ((lid >> 3) & 1) * 16;
          ldmatrix_x4(bfr[np][0], bfr[np][1], bfr[np][2], bfr[np][3],
                      sb + row * 128 + (kb ^ ((row & 7) << 4)));
        } else {
          // transposed load from V[tok][e]: k-rows, e-cols
          const int krow = kk * 16 + ((lid >> 3) & 1) * 8 + (lid & 7);
          const int colb = (wn * 64 + np * 16 + ((lid >> 4) & 1) * 8) * 2;
          ldmatrix_x4_trans(bfr[np][0], bfr[np][1], bfr[np][2], bfr[np][3],
                            sb + krow * 256 + (colb ^ ((krow & 7) << 4)));
        }
      }
#pragma unroll
      for (int mt = 0; mt < 2; ++mt)
#pragma unroll
        for (int nt = 0; nt < 8; ++nt)
          mma_fp16(acc[mt][nt], af[mt], bfr[nt >> 1][(nt & 1) * 2],
                   bfr[nt >> 1][(nt & 1) * 2 + 1]);
    }
  }

  // ---- epilogue: fragment (c0,c1)=(m, n..n+1), (c2,c3)=(m+8, n..n+1) ----
#pragma unroll
  for (int mt = 0; mt < 2; ++mt) {
#pragma unroll
    for (int nt = 0; nt < 8; ++nt) {
      const int m = row0 + wm * 32 + mt * 16 + (lid >> 2);
      const int n = col0 + wn * 64 + nt * 8 + 2 * (lid & 3);
      const float* cf = acc[mt][nt];
      if constexpr (MODE == 0) {
        __half* C = (bz == 0) ? g_Q16 : (bz == 1) ? g_K16 : g_V16;
#pragma unroll
        for (int hh = 0; hh < 2; ++hh) {
          const size_t o = (size_t)(m + hh * 8) * D_ + n;
          *(__half2*)(C + o) = __floats2half2_rn(cf[hh * 2], cf[hh * 2 + 1]);
        }
      } else if constexpr (MODE == 1) {
#pragma unroll
        for (int hh = 0; hh < 2; ++hh) {
          float* sp = g_S + ((size_t)bz * N_ + m + hh * 8) * N_ + n;
          sp[0] = cf[hh * 2] * SCALE;
          sp[1] = cf[hh * 2 + 1] * SCALE;
        }
      } else {
#pragma unroll
        for (int hh = 0; hh < 2; ++hh) {
          float* op = out + ((size_t)bz * N_ + m + hh * 8) * D_ + n;
          op[0] = cf[hh * 2];
          op[1] = cf[hh * 2 + 1];
        }
      }
    }
  }
}

// ---------------------------------------------------------------------------
// Conversions
// ---------------------------------------------------------------------------
__global__ __launch_bounds__(256) void conv_x_kernel(const float* __restrict__ x) {
  size_t i = ((size_t)blockIdx.x * 256 + threadIdx.x) * 4;
  float4 v = *(const float4*)(x + i);
  __half2* o = (__half2*)(g_x16 + i);
  o[0] = __floats2half2_rn(v.x, v.y);
  o[1] = __floats2half2_rn(v.z, v.w);
}

// transpose-convert W[d][e] -> Wt16[e][d]
__global__ __launch_bounds__(256) void conv_w_kernel(const float* __restrict__ Wq,
                                                     const float* __restrict__ Wk,
                                                     const float* __restrict__ Wv) {
  const float* W = (blockIdx.z == 0) ? Wq : (blockIdx.z == 1) ? Wk : Wv;
  __half* T = g_Wt16[blockIdx.z];
  __shared__ float t[32][33];
  int tx = threadIdx.x & 31, ty = threadIdx.x >> 5;  // 32 x 8
  int d0 = blockIdx.y * 32, e0 = blockIdx.x * 32;
#pragma unroll
  for (int i = 0; i < 4; ++i)
    t[ty + i * 8][tx] = W[(size_t)(d0 + ty + i * 8) * D_ + e0 + tx];
  __syncthreads();
#pragma unroll
  for (int i = 0; i < 4; ++i)
    T[(size_t)(e0 + ty + i * 8) * D_ + d0 + tx] = __float2half_rn(t[tx][ty + i * 8]);
}

// ---------------------------------------------------------------------------
// Causal softmax, single gmem pass: row cached in smem, shuffle reductions.
// Writes P fp16 with zeros up to the 128-aligned causal tile bound (what the
// PV GEMM actually reads).
// ---------------------------------------------------------------------------
__global__ __launch_bounds__(256) void softmax_kernel() {
  const int q = blockIdx.x, b = blockIdx.y;
  const float* row = g_S + ((size_t)b * N_ + q) * N_;
  __half* ph = g_P16 + ((size_t)b * N_ + q) * N_;
  const int L = q + 1;
  const int wlim = ((q >> 7) + 1) << 7;  // PV reads cols [0, wlim)
  const int tid = threadIdx.x;

  __shared__ float buf[N_];
  __shared__ float redm[8], reds[8];

  // pass 1: load row -> smem, local max
  float m = -1e30f;
  for (int k = tid; k < L; k += 256) {
    float v = row[k];
    buf[k] = v;
    m = fmaxf(m, v);
  }
#pragma unroll
  for (int o = 16; o; o >>= 1) m = fmaxf(m, __shfl_xor_sync(~0u, m, o));
  if ((tid & 31) == 0) redm[tid >> 5] = m;
  __syncthreads();
  float m0 = redm[0];
#pragma unroll
  for (int w = 1; w < 8; ++w) m0 = fmaxf(m0, redm[w]);

  // pass 2 (smem): exp and local sum
  float sum = 0.f;
  const float c = 1.44269504f;
  for (int k = tid; k < L; k += 256) {
    float e = exp2f((buf[k] - m0) * c);
    buf[k] = e;
    sum += e;
  }
#pragma unroll
  for (int o = 16; o; o >>= 1) sum += __shfl_xor_sync(~0u, sum, o);
  if ((tid & 31) == 0) reds[tid >> 5] = sum;
  __syncthreads();
  float s0 = 0.f;
#pragma unroll
  for (int w = 0; w < 8; ++w) s0 += reds[w];
  const float inv = 1.f / s0;

  // pass 3 (smem): normalize and store fp16 (+ zero pad to tile bound)
  for (int k = tid; k < wlim; k += 256)
    ph[k] = __float2half_rn(k < L ? buf[k] * inv : 0.f);
}

// ---------------------------------------------------------------------------
extern "C" void kernel_launch(void* const* d_in, const int* in_sizes, int n_in,
                              void* d_out, int out_size) {
  const float* x  = (const float*)d_in[0];
  const float* Wq = (const float*)d_in[1];
  const float* Wk = (const float*)d_in[2];
  const float* Wv = (const float*)d_in[3];
  float* out = (float*)d_out;

  cudaFuncSetAttribute(gemm_tc<0>, cudaFuncAttributeMaxDynamicSharedMemorySize,
                       SMEM_DYN);
  cudaFuncSetAttribute(gemm_tc<1>, cudaFuncAttributeMaxDynamicSharedMemorySize,
                       SMEM_DYN);
  cudaFuncSetAttribute(gemm_tc<2>, cudaFuncAttributeMaxDynamicSharedMemorySize,
                       SMEM_DYN);

  // 1) convert inputs to fp16
  conv_x_kernel<<<(M_ * D_) / (256 * 4), 256>>>(x);
  conv_w_kernel<<<dim3(D_ / 32, D_ / 32, 3), 256>>>(Wq, Wk, Wv);
  // 2) QKV projections: C[8192,1024], 128x128 tiles
  gemm_tc<0><<<dim3(D_ / 128, M_ / 128, 3), 256, SMEM_DYN>>>(nullptr);
  // 3) scores S = scale * Q K^T (tiles above the diagonal skipped)
  gemm_tc<1><<<dim3(N_ / 128, N_ / 128, B_), 256, SMEM_DYN>>>(nullptr);
  // 4) softmax -> P fp16
  softmax_kernel<<<dim3(N_, B_), 256>>>();
  // 5) O = P V (causally bounded K loop, heavy tiles first, V loaded direct)
  gemm_tc<2><<<dim3(D_ / 128, N_ / 128, B_), 256, SMEM_DYN>>>(out);
}